// round 8
// baseline (speedup 1.0000x reference)
#include <cuda_runtime.h>
#include <cuda_fp16.h>
#include <cstdint>

// Problem dims
#define BROWS 8192
#define NDIM  4096   // K of GEMM (SV dim)
#define MDIM  4096   // output cols (SU dim)

// -------- scratch (device globals; no allocation) --------
__device__ __half g_A[(size_t)BROWS * NDIM];   // x_rht fp16
__device__ __half g_W[(size_t)MDIM * NDIM];    // decoded W * Wscale, fp16
__device__ __half g_C[(size_t)BROWS * MDIM];   // y_rht fp16

// ====================== PTX helpers (baseline ISA only, sm_80+) ======================
__device__ __forceinline__ uint32_t smem_u32(const void* p) {
    uint32_t a;
    asm("{ .reg .u64 t; cvta.to.shared.u64 t, %1; cvt.u32.u64 %0, t; }" : "=r"(a) : "l"(p));
    return a;
}
__device__ __forceinline__ void cp16(uint32_t s, const void* g) {
    asm volatile("cp.async.cg.shared.global [%0], [%1], 16;" :: "r"(s), "l"(g));
}
__device__ __forceinline__ void cp_commit() { asm volatile("cp.async.commit_group;" ::: "memory"); }

__device__ __forceinline__ void ldsm4(uint32_t* r, uint32_t addr) {
    asm volatile("ldmatrix.sync.aligned.m8n8.x4.shared.b16 {%0,%1,%2,%3}, [%4];"
                 : "=r"(r[0]), "=r"(r[1]), "=r"(r[2]), "=r"(r[3]) : "r"(addr));
}
__device__ __forceinline__ void mma16816(float* c, const uint32_t* a, const uint32_t* b) {
    asm volatile(
        "mma.sync.aligned.m16n8k16.row.col.f32.f16.f16.f32 "
        "{%0,%1,%2,%3}, {%4,%5,%6,%7}, {%8,%9}, {%0,%1,%2,%3};"
        : "+f"(c[0]), "+f"(c[1]), "+f"(c[2]), "+f"(c[3])
        : "r"(a[0]), "r"(a[1]), "r"(a[2]), "r"(a[3]), "r"(b[0]), "r"(b[1]));
}
// SW128 swizzle for GEMM smem
__device__ __forceinline__ uint32_t swz(uint32_t off) { return off ^ ((off >> 3) & 0x70); }

// ====================== FHT v3 ======================
__device__ __forceinline__ void h8(float* v) {
    #pragma unroll
    for (int s = 1; s < 8; s <<= 1) {
        #pragma unroll
        for (int i = 0; i < 8; i++) {
            if ((i & s) == 0) {
                float a = v[i], b = v[i | s];
                v[i]     = a + b;
                v[i | s] = a - b;
            }
        }
    }
}
__device__ __forceinline__ void h16(float* v) {
    #pragma unroll
    for (int s = 1; s < 16; s <<= 1) {
        #pragma unroll
        for (int i = 0; i < 16; i++) {
            if ((i & s) == 0) {
                float a = v[i], b = v[i | s];
                v[i]     = a + b;
                v[i | s] = a - b;
            }
        }
    }
}
// shfl-bfly butterfly over 5 lane bits (element bits 3-7)
__device__ __forceinline__ void shfl_h32(float* v, int lane) {
    #pragma unroll
    for (int m = 1; m < 32; m <<= 1) {
        #pragma unroll
        for (int j = 0; j < 8; j++) {
            float o = __shfl_xor_sync(0xffffffffu, v[j], m);
            v[j] = (lane & m) ? (o - v[j]) : (v[j] + o);
        }
    }
}
// 16B-chunk swizzle for the smem exchange
__device__ __forceinline__ int csw(int c) { return c ^ ((c >> 3) & 7); }

__global__ __launch_bounds__(512) void fht_in_kernel(const float* __restrict__ x,
                                                     const float* __restrict__ sv) {
    __shared__ float s[4096];
    const int t = threadIdx.x;
    const int lane = t & 31;
    const size_t row = blockIdx.x;
    const float* xr = x + row * NDIM;
    float v[8];

    {
        const float4* xp = reinterpret_cast<const float4*>(xr + 8 * t);
        const float4* sp = reinterpret_cast<const float4*>(sv + 8 * t);
        float4 a0 = xp[0], a1 = xp[1], b0 = sp[0], b1 = sp[1];
        v[0] = a0.x * b0.x; v[1] = a0.y * b0.y; v[2] = a0.z * b0.z; v[3] = a0.w * b0.w;
        v[4] = a1.x * b1.x; v[5] = a1.y * b1.y; v[6] = a1.z * b1.z; v[7] = a1.w * b1.w;
    }
    h8(v);                 // bits 0-2
    shfl_h32(v, lane);     // bits 3-7

    {
        float4* s4 = reinterpret_cast<float4*>(s);
        s4[csw(2 * t)]     = make_float4(v[0], v[1], v[2], v[3]);
        s4[csw(2 * t + 1)] = make_float4(v[4], v[5], v[6], v[7]);
    }
    __syncthreads();

    if (t < 256) {
        float w[16];
        #pragma unroll
        for (int k = 0; k < 16; k++) {
            int i = t + 256 * k;
            w[k] = s[csw(i >> 2) * 4 + (i & 3)];
        }
        h16(w);
        __half* ar = g_A + row * NDIM;
        #pragma unroll
        for (int k = 0; k < 16; k++)
            ar[t + 256 * k] = __float2half(w[k] * 0.015625f);
    }
}

__global__ __launch_bounds__(512) void fht_out_kernel(const float* __restrict__ su,
                                                      float* __restrict__ out) {
    __shared__ float s[4096];
    const int t = threadIdx.x;
    const int lane = t & 31;
    const size_t row = blockIdx.x;
    float v[8];

    {
        uint4 raw = *reinterpret_cast<const uint4*>(g_C + row * MDIM + 8 * t);
        const __half2* h = reinterpret_cast<const __half2*>(&raw);
        #pragma unroll
        for (int j = 0; j < 4; j++) {
            float2 f = __half22float2(h[j]);
            v[2 * j] = f.x; v[2 * j + 1] = f.y;
        }
    }
    h8(v);
    shfl_h32(v, lane);

    {
        float4* s4 = reinterpret_cast<float4*>(s);
        s4[csw(2 * t)]     = make_float4(v[0], v[1], v[2], v[3]);
        s4[csw(2 * t + 1)] = make_float4(v[4], v[5], v[6], v[7]);
    }
    __syncthreads();

    if (t < 256) {
        float w[16];
        #pragma unroll
        for (int k = 0; k < 16; k++) {
            int i = t + 256 * k;
            w[k] = s[csw(i >> 2) * 4 + (i & 3)];
        }
        h16(w);
        float* orow = out + row * MDIM;
        #pragma unroll
        for (int k = 0; k < 16; k++) {
            int i = t + 256 * k;
            orow[i] = w[k] * su[i] * 0.015625f;
        }
    }
}

// ====================== W decode ======================
__global__ __launch_bounds__(256) void decode_w_kernel(const int* __restrict__ q1,
                                                       const int* __restrict__ q2,
                                                       const float* __restrict__ cb1,
                                                       const float* __restrict__ cb2,
                                                       const float* __restrict__ wsc_p,
                                                       const float* __restrict__ irs_p) {
    __shared__ float s1[2048], s2[2048];
    const float ws = *wsc_p;
    const float ir = *irs_p;
    for (int i = threadIdx.x; i < 2048; i += 256) {
        s1[i] = cb1[i] * ws;
        s2[i] = cb2[i] * (ir * ws);
    }
    __syncthreads();
    const size_t idx = (size_t)blockIdx.x * 256 + threadIdx.x;  // over M*G = 2M
    const int i1 = q1[idx] * 8;
    const int i2 = q2[idx] * 8;
    __half2 o[4];
    #pragma unroll
    for (int j = 0; j < 4; j++) {
        float a = s1[i1 + 2 * j]     + s2[i2 + 2 * j];
        float b = s1[i1 + 2 * j + 1] + s2[i2 + 2 * j + 1];
        o[j] = __floats2half2_rn(a, b);
    }
    *reinterpret_cast<uint4*>(g_W + idx * 8) = *reinterpret_cast<uint4*>(o);
}

// ====================== GEMM: C = A @ W^T (fp16 in, fp32 accum, fp16 out) ======================
// 256 threads, block tile 128x256, warp tile 64x64, 4-stage cp.async, 1 barrier/iter,
// double-buffered ldmatrix fragments (LDSM latency hidden under MMA stream).
static constexpr int BM = 128;
static constexpr int BN = 256;
static constexpr int BK = 64;                    // halfs per K chunk (=128B row)
static constexpr int STAGES = 4;
static constexpr int NIT = NDIM / BK;            // 64
static constexpr int A_STAGE = BM * 128;         // 16384 B
static constexpr int B_STAGE = BN * 128;         // 32768 B
static constexpr int STAGE_BYTES = A_STAGE + B_STAGE;         // 49152
static constexpr int GEMM_SMEM = STAGES * STAGE_BYTES;        // 196608

__device__ __forceinline__ void load_stage(uint32_t sb, int it, int s,
                                           size_t aRow0, size_t bRow0, int tid) {
    const int c  = tid & 7;         // 16B chunk within 128B row
    const int r0 = tid >> 3;        // 0..31
    const char* ag = (const char*)(g_A + aRow0 * NDIM + (size_t)it * BK) + c * 16;
    const char* bg = (const char*)(g_W + bRow0 * NDIM + (size_t)it * BK) + c * 16;
    const uint32_t as = sb + s * STAGE_BYTES;
    const uint32_t bs = as + A_STAGE;
    #pragma unroll
    for (int rr = 0; rr < 4; rr++) {
        int r = r0 + rr * 32;
        cp16(as + swz(r * 128 + c * 16), ag + (size_t)r * (NDIM * 2));
    }
    #pragma unroll
    for (int rr = 0; rr < 8; rr++) {
        int r = r0 + rr * 32;
        cp16(bs + swz(r * 128 + c * 16), bg + (size_t)r * (NDIM * 2));
    }
}

__global__ __launch_bounds__(256)
void gemm_kernel() {
    extern __shared__ char smem[];
    const uint32_t sb = smem_u32(smem);
    const int tid = threadIdx.x;
    const int wid = tid >> 5;
    const int lid = tid & 31;
    const int wm  = wid & 1;        // 2 warps along M (64 rows each)
    const int wn  = wid >> 1;       // 4 warps along N (64 cols each)

    const size_t aRow0 = (size_t)blockIdx.y * BM;   // batch rows
    const size_t bRow0 = (size_t)blockIdx.x * BN;   // weight rows (= output cols)

    // ldmatrix lane geometry (x4: tile l>>3, row l&7)
    const int t_ld   = lid >> 3;
    const int r_ld   = lid & 7;
    const int mo_ld  = (t_ld & 1) * 8 + r_ld;   // row offset within 16-row frag
    const int ko_ld  = (t_ld >> 1) * 8;         // k offset within k16 frag

    // precomputed swizzled smem byte offsets (stage-relative)
    uint32_t aOff[4], bOff[4];
    #pragma unroll
    for (int mt = 0; mt < 4; mt++)
        aOff[mt] = swz((wm * 64 + mt * 16 + mo_ld) * 128 + ko_ld * 2);
    #pragma unroll
    for (int nt = 0; nt < 4; nt++)
        bOff[nt] = swz((wn * 64 + nt * 16 + mo_ld) * 128 + ko_ld * 2);
    // k16 step advances k by 16 halfs = 32B within the 128B row; swizzle only
    // permutes bits[6:4] by row bits, so adding ks*32 pre-swizzle == XOR-free:
    // swz(x + ks*32) for fixed row = swz(x) ^ (ks*32 with row-xor applied)... compute per-step fresh:
    // (we just re-add: swz distributes because ks*32 only touches bits[5:0]|bit6? 32B steps touch bit5,bit6)
    // safest: keep full recompute per (frag, ks) via base tables:
    uint32_t aS[4][4], bS[4][4];
    #pragma unroll
    for (int ks = 0; ks < 4; ks++) {
        #pragma unroll
        for (int mt = 0; mt < 4; mt++)
            aS[ks][mt] = swz((wm * 64 + mt * 16 + mo_ld) * 128 + (ks * 16 + ko_ld) * 2);
        #pragma unroll
        for (int nt = 0; nt < 4; nt++)
            bS[ks][nt] = swz((wn * 64 + nt * 16 + mo_ld) * 128 + (ks * 16 + ko_ld) * 2);
    }
    (void)aOff; (void)bOff;

    float acc[4][8][4];              // [mt][nt8][reg]
    #pragma unroll
    for (int i = 0; i < 4; i++)
        #pragma unroll
        for (int j = 0; j < 8; j++)
            #pragma unroll
            for (int q = 0; q < 4; q++) acc[i][j][q] = 0.0f;

    // prologue: fill 3 of 4 stages
    #pragma unroll
    for (int s = 0; s < STAGES - 1; s++) {
        load_stage(sb, s, s, aRow0, bRow0, tid);
        cp_commit();
    }

    uint32_t af[2][4][4], bf[2][4][4];   // double-buffered fragments

    for (int it = 0; it < NIT; ++it) {
        const int s = it & 3;
        asm volatile("cp.async.wait_group %0;" :: "n"(STAGES - 2) : "memory");
        __syncthreads();   // single barrier per iter: also protects slot (it+3)&3 refill

        // issue next global->smem stage FIRST so its latency overlaps this iter's math
        if (it + STAGES - 1 < NIT)
            load_stage(sb, it + STAGES - 1, (it + STAGES - 1) & 3, aRow0, bRow0, tid);
        cp_commit();

        const uint32_t As = sb + s * STAGE_BYTES;
        const uint32_t Bs = As + A_STAGE;

        // preload fragments for ks=0
        #pragma unroll
        for (int mt = 0; mt < 4; mt++) ldsm4(af[0][mt], As + aS[0][mt]);
        #pragma unroll
        for (int nt = 0; nt < 4; nt++) ldsm4(bf[0][nt], Bs + bS[0][nt]);

        #pragma unroll
        for (int ks = 0; ks < 4; ks++) {
            const int cur = ks & 1, nxt = cur ^ 1;
            if (ks < 3) {
                #pragma unroll
                for (int mt = 0; mt < 4; mt++) ldsm4(af[nxt][mt], As + aS[ks + 1][mt]);
                #pragma unroll
                for (int nt = 0; nt < 4; nt++) ldsm4(bf[nxt][nt], Bs + bS[ks + 1][nt]);
            }
            #pragma unroll
            for (int mt = 0; mt < 4; mt++) {
                #pragma unroll
                for (int nt = 0; nt < 8; nt++) {
                    uint32_t b2[2] = { bf[cur][nt >> 1][nt & 1], bf[cur][nt >> 1][2 + (nt & 1)] };
                    mma16816(acc[mt][nt], af[cur][mt], b2);
                }
            }
        }
    }

    // epilogue: m16n8 c-frag: lane -> (row = lid>>2 [+8], col = (lid&3)*2)
    const int gid = lid >> 2;
    const int tig = lid & 3;
    #pragma unroll
    for (int mt = 0; mt < 4; mt++) {
        size_t row0 = aRow0 + (size_t)(wm * 64 + mt * 16 + gid);
        #pragma unroll
        for (int nt = 0; nt < 8; nt++) {
            size_t col = bRow0 + (size_t)(wn * 64 + nt * 8 + tig * 2);
            __half2* p0 = reinterpret_cast<__half2*>(g_C + row0 * MDIM + col);
            __half2* p1 = reinterpret_cast<__half2*>(g_C + (row0 + 8) * MDIM + col);
            *p0 = __floats2half2_rn(acc[mt][nt][0], acc[mt][nt][1]);
            *p1 = __floats2half2_rn(acc[mt][nt][2], acc[mt][nt][3]);
        }
    }
}

// ====================== launch ======================
extern "C" void kernel_launch(void* const* d_in, const int* in_sizes, int n_in,
                              void* d_out, int out_size) {
    (void)in_sizes; (void)n_in; (void)out_size;
    const float* x   = (const float*)d_in[0];
    const int*   q1  = (const int*)  d_in[1];
    const int*   q2  = (const int*)  d_in[2];
    const float* su  = (const float*)d_in[3];
    const float* sv  = (const float*)d_in[4];
    const float* cb1 = (const float*)d_in[5];
    const float* cb2 = (const float*)d_in[6];
    const float* wsc = (const float*)d_in[7];
    const float* irs = (const float*)d_in[8];
    float* out = (float*)d_out;

    cudaFuncSetAttribute(gemm_kernel, cudaFuncAttributeMaxDynamicSharedMemorySize, GEMM_SMEM);

    fht_in_kernel<<<BROWS, 512>>>(x, sv);
    decode_w_kernel<<<(MDIM * 512) / 256, 256>>>(q1, q2, cb1, cb2, wsc, irs);
    gemm_kernel<<<dim3(MDIM / BN, BROWS / BM), 256, GEMM_SMEM>>>();
    fht_out_kernel<<<BROWS, 512>>>(su, out);
}

// round 13
// speedup vs baseline: 1.0633x; 1.0633x over previous
#include <cuda_runtime.h>
#include <cuda_fp16.h>
#include <cstdint>

// Problem dims
#define BROWS 8192
#define NDIM  4096   // K of GEMM (SV dim)
#define MDIM  4096   // output cols (SU dim)

// -------- scratch (device globals; no allocation) --------
__device__ __half g_A[(size_t)BROWS * NDIM];   // x_rht fp16
__device__ __half g_W[(size_t)MDIM * NDIM];    // decoded W * Wscale, fp16
__device__ __half g_C[(size_t)BROWS * MDIM];   // y_rht fp16

// ====================== PTX helpers (baseline ISA only, sm_80+) ======================
__device__ __forceinline__ uint32_t smem_u32(const void* p) {
    uint32_t a;
    asm("{ .reg .u64 t; cvta.to.shared.u64 t, %1; cvt.u32.u64 %0, t; }" : "=r"(a) : "l"(p));
    return a;
}
__device__ __forceinline__ void cp16(uint32_t s, const void* g) {
    asm volatile("cp.async.cg.shared.global [%0], [%1], 16;" :: "r"(s), "l"(g));
}
__device__ __forceinline__ void cp_commit() { asm volatile("cp.async.commit_group;" ::: "memory"); }

__device__ __forceinline__ void ldsm4(uint32_t* r, uint32_t addr) {
    asm volatile("ldmatrix.sync.aligned.m8n8.x4.shared.b16 {%0,%1,%2,%3}, [%4];"
                 : "=r"(r[0]), "=r"(r[1]), "=r"(r[2]), "=r"(r[3]) : "r"(addr));
}
__device__ __forceinline__ void mma16816(float* c, const uint32_t* a, const uint32_t* b) {
    asm volatile(
        "mma.sync.aligned.m16n8k16.row.col.f32.f16.f16.f32 "
        "{%0,%1,%2,%3}, {%4,%5,%6,%7}, {%8,%9}, {%0,%1,%2,%3};"
        : "+f"(c[0]), "+f"(c[1]), "+f"(c[2]), "+f"(c[3])
        : "r"(a[0]), "r"(a[1]), "r"(a[2]), "r"(a[3]), "r"(b[0]), "r"(b[1]));
}
// SW128 swizzle for GEMM smem
__device__ __forceinline__ uint32_t swz(uint32_t off) { return off ^ ((off >> 3) & 0x70); }

// ====================== FHT v3 ======================
__device__ __forceinline__ void h8(float* v) {
    #pragma unroll
    for (int s = 1; s < 8; s <<= 1) {
        #pragma unroll
        for (int i = 0; i < 8; i++) {
            if ((i & s) == 0) {
                float a = v[i], b = v[i | s];
                v[i]     = a + b;
                v[i | s] = a - b;
            }
        }
    }
}
__device__ __forceinline__ void h16(float* v) {
    #pragma unroll
    for (int s = 1; s < 16; s <<= 1) {
        #pragma unroll
        for (int i = 0; i < 16; i++) {
            if ((i & s) == 0) {
                float a = v[i], b = v[i | s];
                v[i]     = a + b;
                v[i | s] = a - b;
            }
        }
    }
}
// shfl-bfly butterfly over 5 lane bits (element bits 3-7)
__device__ __forceinline__ void shfl_h32(float* v, int lane) {
    #pragma unroll
    for (int m = 1; m < 32; m <<= 1) {
        #pragma unroll
        for (int j = 0; j < 8; j++) {
            float o = __shfl_xor_sync(0xffffffffu, v[j], m);
            v[j] = (lane & m) ? (o - v[j]) : (v[j] + o);
        }
    }
}
// 16B-chunk swizzle for the smem exchange
__device__ __forceinline__ int csw(int c) { return c ^ ((c >> 3) & 7); }

__global__ __launch_bounds__(512) void fht_in_kernel(const float* __restrict__ x,
                                                     const float* __restrict__ sv) {
    __shared__ float s[4096];
    const int t = threadIdx.x;
    const int lane = t & 31;
    const size_t row = blockIdx.x;
    const float* xr = x + row * NDIM;
    float v[8];

    {
        const float4* xp = reinterpret_cast<const float4*>(xr + 8 * t);
        const float4* sp = reinterpret_cast<const float4*>(sv + 8 * t);
        float4 a0 = xp[0], a1 = xp[1], b0 = sp[0], b1 = sp[1];
        v[0] = a0.x * b0.x; v[1] = a0.y * b0.y; v[2] = a0.z * b0.z; v[3] = a0.w * b0.w;
        v[4] = a1.x * b1.x; v[5] = a1.y * b1.y; v[6] = a1.z * b1.z; v[7] = a1.w * b1.w;
    }
    h8(v);                 // bits 0-2
    shfl_h32(v, lane);     // bits 3-7

    {
        float4* s4 = reinterpret_cast<float4*>(s);
        s4[csw(2 * t)]     = make_float4(v[0], v[1], v[2], v[3]);
        s4[csw(2 * t + 1)] = make_float4(v[4], v[5], v[6], v[7]);
    }
    __syncthreads();

    if (t < 256) {
        float w[16];
        #pragma unroll
        for (int k = 0; k < 16; k++) {
            int i = t + 256 * k;
            w[k] = s[csw(i >> 2) * 4 + (i & 3)];
        }
        h16(w);
        __half* ar = g_A + row * NDIM;
        #pragma unroll
        for (int k = 0; k < 16; k++)
            ar[t + 256 * k] = __float2half(w[k] * 0.015625f);
    }
}

__global__ __launch_bounds__(512) void fht_out_kernel(const float* __restrict__ su,
                                                      float* __restrict__ out) {
    __shared__ float s[4096];
    const int t = threadIdx.x;
    const int lane = t & 31;
    const size_t row = blockIdx.x;
    float v[8];

    {
        uint4 raw = *reinterpret_cast<const uint4*>(g_C + row * MDIM + 8 * t);
        const __half2* h = reinterpret_cast<const __half2*>(&raw);
        #pragma unroll
        for (int j = 0; j < 4; j++) {
            float2 f = __half22float2(h[j]);
            v[2 * j] = f.x; v[2 * j + 1] = f.y;
        }
    }
    h8(v);
    shfl_h32(v, lane);

    {
        float4* s4 = reinterpret_cast<float4*>(s);
        s4[csw(2 * t)]     = make_float4(v[0], v[1], v[2], v[3]);
        s4[csw(2 * t + 1)] = make_float4(v[4], v[5], v[6], v[7]);
    }
    __syncthreads();

    if (t < 256) {
        float w[16];
        #pragma unroll
        for (int k = 0; k < 16; k++) {
            int i = t + 256 * k;
            w[k] = s[csw(i >> 2) * 4 + (i & 3)];
        }
        h16(w);
        float* orow = out + row * MDIM;
        #pragma unroll
        for (int k = 0; k < 16; k++) {
            int i = t + 256 * k;
            orow[i] = w[k] * su[i] * 0.015625f;
        }
    }
}

// ====================== W decode ======================
__global__ __launch_bounds__(256) void decode_w_kernel(const int* __restrict__ q1,
                                                       const int* __restrict__ q2,
                                                       const float* __restrict__ cb1,
                                                       const float* __restrict__ cb2,
                                                       const float* __restrict__ wsc_p,
                                                       const float* __restrict__ irs_p) {
    __shared__ float s1[2048], s2[2048];
    const float ws = *wsc_p;
    const float ir = *irs_p;
    for (int i = threadIdx.x; i < 2048; i += 256) {
        s1[i] = cb1[i] * ws;
        s2[i] = cb2[i] * (ir * ws);
    }
    __syncthreads();
    const size_t idx = (size_t)blockIdx.x * 256 + threadIdx.x;  // over M*G = 2M
    const int i1 = q1[idx] * 8;
    const int i2 = q2[idx] * 8;
    __half2 o[4];
    #pragma unroll
    for (int j = 0; j < 4; j++) {
        float a = s1[i1 + 2 * j]     + s2[i2 + 2 * j];
        float b = s1[i1 + 2 * j + 1] + s2[i2 + 2 * j + 1];
        o[j] = __floats2half2_rn(a, b);
    }
    *reinterpret_cast<uint4*>(g_W + idx * 8) = *reinterpret_cast<uint4*>(o);
}

// ====================== GEMM: C = A @ W^T (fp16 in, fp32 accum, fp16 out) ======================
// 2 CTAs/SM: 256 threads, block tile 128x128, warp tile 64x32, 3-stage cp.async,
// 1 barrier/iter. Cross-CTA overlap hides barrier + LDSM stalls.
// NOTE: k16-step advance within a 128B row is swz(x)^d, NOT swz(x)+d.
static constexpr int BM = 128;
static constexpr int BN = 128;
static constexpr int BK = 64;                    // halfs per K chunk (=128B row)
static constexpr int STAGES = 3;
static constexpr int NIT = NDIM / BK;            // 64
static constexpr int A_STAGE = BM * 128;         // 16384 B
static constexpr int B_STAGE = BN * 128;         // 16384 B
static constexpr int STAGE_BYTES = A_STAGE + B_STAGE;         // 32768
static constexpr int GEMM_SMEM = STAGES * STAGE_BYTES;        // 98304 (x2 CTAs = 192K)

__device__ __forceinline__ void load_stage(uint32_t sb, int it, int s,
                                           size_t aRow0, size_t bRow0, int tid) {
    const int c  = tid & 7;         // 16B chunk within 128B row
    const int r0 = tid >> 3;        // 0..31
    const char* ag = (const char*)(g_A + aRow0 * NDIM + (size_t)it * BK) + c * 16;
    const char* bg = (const char*)(g_W + bRow0 * NDIM + (size_t)it * BK) + c * 16;
    const uint32_t as = sb + s * STAGE_BYTES;
    const uint32_t bs = as + A_STAGE;
    #pragma unroll
    for (int rr = 0; rr < 4; rr++) {
        int r = r0 + rr * 32;
        cp16(as + swz(r * 128 + c * 16), ag + (size_t)r * (NDIM * 2));
    }
    #pragma unroll
    for (int rr = 0; rr < 4; rr++) {
        int r = r0 + rr * 32;
        cp16(bs + swz(r * 128 + c * 16), bg + (size_t)r * (NDIM * 2));
    }
}

__global__ __launch_bounds__(256, 2)
void gemm_kernel() {
    extern __shared__ char smem[];
    const uint32_t sb = smem_u32(smem);
    const int tid = threadIdx.x;
    const int wid = tid >> 5;
    const int lid = tid & 31;
    const int wm  = wid & 1;        // 2 warps along M (64 rows each)
    const int wn  = wid >> 1;       // 4 warps along N (32 cols each)

    const size_t aRow0 = (size_t)blockIdx.y * BM;   // batch rows
    const size_t bRow0 = (size_t)blockIdx.x * BN;   // weight rows (= output cols)

    // ldmatrix lane geometry (x4: tile l>>3, row l&7)
    const int t_ld   = lid >> 3;
    const int r_ld   = lid & 7;
    const int mo_ld  = (t_ld & 1) * 8 + r_ld;   // row offset within 16-row frag
    const int ko_ld  = (t_ld >> 1) * 8;         // k offset within k16 frag

    // base swizzled offsets; k16-step advance is XOR with ks*32 (bits 5-6,
    // disjoint from pre-swizzle low bits, commutes with the XOR swizzle)
    uint32_t aOff[4], bOff[2];
    #pragma unroll
    for (int mt = 0; mt < 4; mt++)
        aOff[mt] = swz((wm * 64 + mt * 16 + mo_ld) * 128 + ko_ld * 2);
    #pragma unroll
    for (int nt = 0; nt < 2; nt++)
        bOff[nt] = swz((wn * 32 + nt * 16 + mo_ld) * 128 + ko_ld * 2);

    float acc[4][4][4];              // [mt][nt8][reg] = 64 regs
    #pragma unroll
    for (int i = 0; i < 4; i++)
        #pragma unroll
        for (int j = 0; j < 4; j++)
            #pragma unroll
            for (int q = 0; q < 4; q++) acc[i][j][q] = 0.0f;

    // prologue: fill 2 of 3 stages
    #pragma unroll
    for (int s = 0; s < STAGES - 1; s++) {
        load_stage(sb, s, s, aRow0, bRow0, tid);
        cp_commit();
    }

    int s = 0;
    for (int it = 0; it < NIT; ++it) {
        asm volatile("cp.async.wait_group %0;" :: "n"(STAGES - 2) : "memory");
        __syncthreads();   // single barrier: also protects refill of slot it+2

        // issue next stage first so global latency overlaps this iter's math
        if (it + STAGES - 1 < NIT) {
            int sn = s + 2; if (sn >= STAGES) sn -= STAGES;
            load_stage(sb, it + STAGES - 1, sn, aRow0, bRow0, tid);
        }
        cp_commit();

        const uint32_t As = sb + s * STAGE_BYTES;
        const uint32_t Bs = As + A_STAGE;

        #pragma unroll
        for (int ks = 0; ks < 4; ks++) {
            uint32_t af[4][4];
            #pragma unroll
            for (int mt = 0; mt < 4; mt++) ldsm4(af[mt], As + (aOff[mt] ^ (ks * 32)));
            uint32_t bf[2][4];
            #pragma unroll
            for (int nt = 0; nt < 2; nt++) ldsm4(bf[nt], Bs + (bOff[nt] ^ (ks * 32)));
            #pragma unroll
            for (int mt = 0; mt < 4; mt++) {
                #pragma unroll
                for (int nt = 0; nt < 4; nt++) {
                    uint32_t b2[2] = { bf[nt >> 1][nt & 1], bf[nt >> 1][2 + (nt & 1)] };
                    mma16816(acc[mt][nt], af[mt], b2);
                }
            }
        }
        if (++s == STAGES) s = 0;
    }

    // epilogue: m16n8 c-frag: lane -> (row = lid>>2 [+8], col = (lid&3)*2)
    const int gid = lid >> 2;
    const int tig = lid & 3;
    #pragma unroll
    for (int mt = 0; mt < 4; mt++) {
        size_t row0 = aRow0 + (size_t)(wm * 64 + mt * 16 + gid);
        #pragma unroll
        for (int nt = 0; nt < 4; nt++) {
            size_t col = bRow0 + (size_t)(wn * 32 + nt * 8 + tig * 2);
            __half2* p0 = reinterpret_cast<__half2*>(g_C + row0 * MDIM + col);
            __half2* p1 = reinterpret_cast<__half2*>(g_C + (row0 + 8) * MDIM + col);
            *p0 = __floats2half2_rn(acc[mt][nt][0], acc[mt][nt][1]);
            *p1 = __floats2half2_rn(acc[mt][nt][2], acc[mt][nt][3]);
        }
    }
}

// ====================== launch ======================
extern "C" void kernel_launch(void* const* d_in, const int* in_sizes, int n_in,
                              void* d_out, int out_size) {
    (void)in_sizes; (void)n_in; (void)out_size;
    const float* x   = (const float*)d_in[0];
    const int*   q1  = (const int*)  d_in[1];
    const int*   q2  = (const int*)  d_in[2];
    const float* su  = (const float*)d_in[3];
    const float* sv  = (const float*)d_in[4];
    const float* cb1 = (const float*)d_in[5];
    const float* cb2 = (const float*)d_in[6];
    const float* wsc = (const float*)d_in[7];
    const float* irs = (const float*)d_in[8];
    float* out = (float*)d_out;

    cudaFuncSetAttribute(gemm_kernel, cudaFuncAttributeMaxDynamicSharedMemorySize, GEMM_SMEM);

    fht_in_kernel<<<BROWS, 512>>>(x, sv);
    decode_w_kernel<<<(MDIM * 512) / 256, 256>>>(q1, q2, cb1, cb2, wsc, irs);
    gemm_kernel<<<dim3(MDIM / BN, BROWS / BM), 256, GEMM_SMEM>>>();
    fht_out_kernel<<<BROWS, 512>>>(su, out);
}

// round 15
// speedup vs baseline: 1.0731x; 1.0093x over previous
#include <cuda_runtime.h>
#include <cuda_fp16.h>
#include <cstdint>

// Problem dims
#define BROWS 8192
#define NDIM  4096   // K of GEMM (SV dim)
#define MDIM  4096   // output cols (SU dim)

// -------- scratch (device globals; no allocation) --------
__device__ __half g_A[(size_t)BROWS * NDIM];   // x_rht fp16
__device__ __half g_W[(size_t)MDIM * NDIM];    // decoded W * Wscale, fp16
__device__ __half g_C[(size_t)BROWS * MDIM];   // y_rht fp16

// ====================== PTX helpers (baseline ISA only, sm_80+) ======================
__device__ __forceinline__ uint32_t smem_u32(const void* p) {
    uint32_t a;
    asm("{ .reg .u64 t; cvta.to.shared.u64 t, %1; cvt.u32.u64 %0, t; }" : "=r"(a) : "l"(p));
    return a;
}
__device__ __forceinline__ void cp16(uint32_t s, const void* g) {
    asm volatile("cp.async.cg.shared.global [%0], [%1], 16;" :: "r"(s), "l"(g));
}
__device__ __forceinline__ void cp_commit() { asm volatile("cp.async.commit_group;" ::: "memory"); }

__device__ __forceinline__ void ldsm4(uint32_t* r, uint32_t addr) {
    asm volatile("ldmatrix.sync.aligned.m8n8.x4.shared.b16 {%0,%1,%2,%3}, [%4];"
                 : "=r"(r[0]), "=r"(r[1]), "=r"(r[2]), "=r"(r[3]) : "r"(addr));
}
__device__ __forceinline__ void mma16816(float* c, const uint32_t* a, const uint32_t* b) {
    asm volatile(
        "mma.sync.aligned.m16n8k16.row.col.f32.f16.f16.f32 "
        "{%0,%1,%2,%3}, {%4,%5,%6,%7}, {%8,%9}, {%0,%1,%2,%3};"
        : "+f"(c[0]), "+f"(c[1]), "+f"(c[2]), "+f"(c[3])
        : "r"(a[0]), "r"(a[1]), "r"(a[2]), "r"(a[3]), "r"(b[0]), "r"(b[1]));
}
// SW128 swizzle for GEMM smem
__device__ __forceinline__ uint32_t swz(uint32_t off) { return off ^ ((off >> 3) & 0x70); }

// ====================== FHT v3 primitives ======================
__device__ __forceinline__ void h8(float* v) {
    #pragma unroll
    for (int s = 1; s < 8; s <<= 1) {
        #pragma unroll
        for (int i = 0; i < 8; i++) {
            if ((i & s) == 0) {
                float a = v[i], b = v[i | s];
                v[i]     = a + b;
                v[i | s] = a - b;
            }
        }
    }
}
__device__ __forceinline__ void h16(float* v) {
    #pragma unroll
    for (int s = 1; s < 16; s <<= 1) {
        #pragma unroll
        for (int i = 0; i < 16; i++) {
            if ((i & s) == 0) {
                float a = v[i], b = v[i | s];
                v[i]     = a + b;
                v[i | s] = a - b;
            }
        }
    }
}
__device__ __forceinline__ void shfl_h32(float* v, int lane) {
    #pragma unroll
    for (int m = 1; m < 32; m <<= 1) {
        #pragma unroll
        for (int j = 0; j < 8; j++) {
            float o = __shfl_xor_sync(0xffffffffu, v[j], m);
            v[j] = (lane & m) ? (o - v[j]) : (v[j] + o);
        }
    }
}
__device__ __forceinline__ int csw(int c) { return c ^ ((c >> 3) & 7); }

// ====================== fused fht_in + W decode ======================
// blocks [0, 8192): FHT of row b; blocks [8192, 12288): decode 512 W groups each.
__global__ __launch_bounds__(512) void fht_in_decode_kernel(
    const float* __restrict__ x, const float* __restrict__ sv,
    const int* __restrict__ q1, const int* __restrict__ q2,
    const float* __restrict__ cb1, const float* __restrict__ cb2,
    const float* __restrict__ wsc_p, const float* __restrict__ irs_p) {
    __shared__ float s[4096];
    const int t = threadIdx.x;

    if (blockIdx.x >= BROWS) {
        // ---- decode branch ----
        float* s1 = s;          // 2048 floats
        float* s2 = s + 2048;   // 2048 floats
        const float ws = *wsc_p;
        const float ir = *irs_p;
        for (int i = t; i < 2048; i += 512) {
            s1[i] = cb1[i] * ws;
            s2[i] = cb2[i] * (ir * ws);
        }
        __syncthreads();
        const size_t idx = (size_t)(blockIdx.x - BROWS) * 512 + t;  // over M*G = 2M
        const int i1 = q1[idx] * 8;
        const int i2 = q2[idx] * 8;
        __half2 o[4];
        #pragma unroll
        for (int j = 0; j < 4; j++) {
            float a = s1[i1 + 2 * j]     + s2[i2 + 2 * j];
            float b = s1[i1 + 2 * j + 1] + s2[i2 + 2 * j + 1];
            o[j] = __floats2half2_rn(a, b);
        }
        *reinterpret_cast<uint4*>(g_W + idx * 8) = *reinterpret_cast<uint4*>(o);
        return;
    }

    // ---- FHT branch ----
    const int lane = t & 31;
    const size_t row = blockIdx.x;
    const float* xr = x + row * NDIM;
    float v[8];
    {
        const float4* xp = reinterpret_cast<const float4*>(xr + 8 * t);
        const float4* sp = reinterpret_cast<const float4*>(sv + 8 * t);
        float4 a0 = xp[0], a1 = xp[1], b0 = sp[0], b1 = sp[1];
        v[0] = a0.x * b0.x; v[1] = a0.y * b0.y; v[2] = a0.z * b0.z; v[3] = a0.w * b0.w;
        v[4] = a1.x * b1.x; v[5] = a1.y * b1.y; v[6] = a1.z * b1.z; v[7] = a1.w * b1.w;
    }
    h8(v);                 // bits 0-2
    shfl_h32(v, lane);     // bits 3-7
    {
        float4* s4 = reinterpret_cast<float4*>(s);
        s4[csw(2 * t)]     = make_float4(v[0], v[1], v[2], v[3]);
        s4[csw(2 * t + 1)] = make_float4(v[4], v[5], v[6], v[7]);
    }
    __syncthreads();
    if (t < 256) {
        float w[16];
        #pragma unroll
        for (int k = 0; k < 16; k++) {
            int i = t + 256 * k;
            w[k] = s[csw(i >> 2) * 4 + (i & 3)];
        }
        h16(w);
        __half* ar = g_A + row * NDIM;
        #pragma unroll
        for (int k = 0; k < 16; k++)
            ar[t + 256 * k] = __float2half(w[k] * 0.015625f);
    }
}

__global__ __launch_bounds__(512) void fht_out_kernel(const float* __restrict__ su,
                                                      float* __restrict__ out) {
    __shared__ float s[4096];
    const int t = threadIdx.x;
    const int lane = t & 31;
    const size_t row = blockIdx.x;
    float v[8];

    {
        uint4 raw = *reinterpret_cast<const uint4*>(g_C + row * MDIM + 8 * t);
        const __half2* h = reinterpret_cast<const __half2*>(&raw);
        #pragma unroll
        for (int j = 0; j < 4; j++) {
            float2 f = __half22float2(h[j]);
            v[2 * j] = f.x; v[2 * j + 1] = f.y;
        }
    }
    h8(v);
    shfl_h32(v, lane);

    {
        float4* s4 = reinterpret_cast<float4*>(s);
        s4[csw(2 * t)]     = make_float4(v[0], v[1], v[2], v[3]);
        s4[csw(2 * t + 1)] = make_float4(v[4], v[5], v[6], v[7]);
    }
    __syncthreads();

    if (t < 256) {
        float w[16];
        #pragma unroll
        for (int k = 0; k < 16; k++) {
            int i = t + 256 * k;
            w[k] = s[csw(i >> 2) * 4 + (i & 3)];
        }
        h16(w);
        float* orow = out + row * MDIM;
        #pragma unroll
        for (int k = 0; k < 16; k++) {
            int i = t + 256 * k;
            orow[i] = w[k] * su[i] * 0.015625f;
        }
    }
}

// ====================== GEMM: C = A @ W^T (fp16 in, fp32 accum, fp16 out) ======================
// 2 CTAs/SM, 128 threads/CTA (4 warps), block tile 128x128, warp tile 64x64,
// 3-stage cp.async, 1 barrier/iter. Warp grid 2x2 => A and B LDSM redundancy
// both 2x (was 4x/2x) => smem crossbar 96KB/iter vs MMA 1024 cyc: tensor-bound.
static constexpr int BM = 128;
static constexpr int BN = 128;
static constexpr int BK = 64;                    // halfs per K chunk (=128B row)
static constexpr int STAGES = 3;
static constexpr int NIT = NDIM / BK;            // 64
static constexpr int A_STAGE = BM * 128;         // 16384 B
static constexpr int B_STAGE = BN * 128;         // 16384 B
static constexpr int STAGE_BYTES = A_STAGE + B_STAGE;         // 32768
static constexpr int GEMM_SMEM = STAGES * STAGE_BYTES;        // 98304 (x2 CTAs = 192K)

__device__ __forceinline__ void load_stage(uint32_t sb, int it, int s,
                                           size_t aRow0, size_t bRow0, int tid) {
    const int c  = tid & 7;         // 16B chunk within 128B row
    const int r0 = tid >> 3;        // 0..15
    const char* ag = (const char*)(g_A + aRow0 * NDIM + (size_t)it * BK) + c * 16;
    const char* bg = (const char*)(g_W + bRow0 * NDIM + (size_t)it * BK) + c * 16;
    const uint32_t as = sb + s * STAGE_BYTES;
    const uint32_t bs = as + A_STAGE;
    #pragma unroll
    for (int rr = 0; rr < 8; rr++) {
        int r = r0 + rr * 16;
        cp16(as + swz(r * 128 + c * 16), ag + (size_t)r * (NDIM * 2));
    }
    #pragma unroll
    for (int rr = 0; rr < 8; rr++) {
        int r = r0 + rr * 16;
        cp16(bs + swz(r * 128 + c * 16), bg + (size_t)r * (NDIM * 2));
    }
}

__global__ __launch_bounds__(128, 2)
void gemm_kernel() {
    extern __shared__ char smem[];
    const uint32_t sb = smem_u32(smem);
    const int tid = threadIdx.x;
    const int wid = tid >> 5;
    const int lid = tid & 31;
    const int wm  = wid & 1;        // 2 warps along M (64 rows each)
    const int wn  = wid >> 1;       // 2 warps along N (64 cols each)

    const size_t aRow0 = (size_t)blockIdx.y * BM;   // batch rows
    const size_t bRow0 = (size_t)blockIdx.x * BN;   // weight rows (= output cols)

    // ldmatrix lane geometry (x4: tile l>>3, row l&7)
    const int t_ld   = lid >> 3;
    const int r_ld   = lid & 7;
    const int mo_ld  = (t_ld & 1) * 8 + r_ld;   // row offset within 16-row frag
    const int ko_ld  = (t_ld >> 1) * 8;         // k offset within k16 frag

    // base swizzled offsets; k16-step advance is XOR with ks*32
    uint32_t aOff[4], bOff[4];
    #pragma unroll
    for (int mt = 0; mt < 4; mt++)
        aOff[mt] = swz((wm * 64 + mt * 16 + mo_ld) * 128 + ko_ld * 2);
    #pragma unroll
    for (int nt = 0; nt < 4; nt++)
        bOff[nt] = swz((wn * 64 + nt * 16 + mo_ld) * 128 + ko_ld * 2);

    float acc[4][8][4];              // [m16 tile][n8 tile][reg] = 128 regs
    #pragma unroll
    for (int i = 0; i < 4; i++)
        #pragma unroll
        for (int j = 0; j < 8; j++)
            #pragma unroll
            for (int q = 0; q < 4; q++) acc[i][j][q] = 0.0f;

    // prologue: fill 2 of 3 stages
    #pragma unroll
    for (int s = 0; s < STAGES - 1; s++) {
        load_stage(sb, s, s, aRow0, bRow0, tid);
        cp_commit();
    }

    int s = 0;
    for (int it = 0; it < NIT; ++it) {
        asm volatile("cp.async.wait_group %0;" :: "n"(STAGES - 2) : "memory");
        __syncthreads();   // single barrier: also protects refill of slot it+2

        // issue next stage first so global latency overlaps this iter's math
        if (it + STAGES - 1 < NIT) {
            int sn = s + 2; if (sn >= STAGES) sn -= STAGES;
            load_stage(sb, it + STAGES - 1, sn, aRow0, bRow0, tid);
        }
        cp_commit();

        const uint32_t As = sb + s * STAGE_BYTES;
        const uint32_t Bs = As + A_STAGE;

        #pragma unroll
        for (int ks = 0; ks < 4; ks++) {
            uint32_t af[4][4];
            #pragma unroll
            for (int mt = 0; mt < 4; mt++) ldsm4(af[mt], As + (aOff[mt] ^ (ks * 32)));
            uint32_t bf[4][4];
            #pragma unroll
            for (int nt = 0; nt < 4; nt++) ldsm4(bf[nt], Bs + (bOff[nt] ^ (ks * 32)));
            #pragma unroll
            for (int mt = 0; mt < 4; mt++) {
                #pragma unroll
                for (int nt = 0; nt < 8; nt++) {
                    uint32_t b2[2] = { bf[nt >> 1][nt & 1], bf[nt >> 1][2 + (nt & 1)] };
                    mma16816(acc[mt][nt], af[mt], b2);
                }
            }
        }
        if (++s == STAGES) s = 0;
    }

    // epilogue: m16n8 c-frag: lane -> (row = lid>>2 [+8], col = (lid&3)*2)
    const int gid = lid >> 2;
    const int tig = lid & 3;
    #pragma unroll
    for (int mt = 0; mt < 4; mt++) {
        size_t row0 = aRow0 + (size_t)(wm * 64 + mt * 16 + gid);
        #pragma unroll
        for (int nt = 0; nt < 8; nt++) {
            size_t col = bRow0 + (size_t)(wn * 64 + nt * 8 + tig * 2);
            __half2* p0 = reinterpret_cast<__half2*>(g_C + row0 * MDIM + col);
            __half2* p1 = reinterpret_cast<__half2*>(g_C + (row0 + 8) * MDIM + col);
            *p0 = __floats2half2_rn(acc[mt][nt][0], acc[mt][nt][1]);
            *p1 = __floats2half2_rn(acc[mt][nt][2], acc[mt][nt][3]);
        }
    }
}

// ====================== launch ======================
extern "C" void kernel_launch(void* const* d_in, const int* in_sizes, int n_in,
                              void* d_out, int out_size) {
    (void)in_sizes; (void)n_in; (void)out_size;
    const float* x   = (const float*)d_in[0];
    const int*   q1  = (const int*)  d_in[1];
    const int*   q2  = (const int*)  d_in[2];
    const float* su  = (const float*)d_in[3];
    const float* sv  = (const float*)d_in[4];
    const float* cb1 = (const float*)d_in[5];
    const float* cb2 = (const float*)d_in[6];
    const float* wsc = (const float*)d_in[7];
    const float* irs = (const float*)d_in[8];
    float* out = (float*)d_out;

    cudaFuncSetAttribute(gemm_kernel, cudaFuncAttributeMaxDynamicSharedMemorySize, GEMM_SMEM);

    // 8192 FHT blocks + 4096 decode blocks in one concurrent launch
    fht_in_decode_kernel<<<BROWS + 4096, 512>>>(x, sv, q1, q2, cb1, cb2, wsc, irs);
    gemm_kernel<<<dim3(MDIM / BN, BROWS / BM), 128, GEMM_SMEM>>>();
    fht_out_kernel<<<BROWS, 512>>>(su, out);
}